// round 3
// baseline (speedup 1.0000x reference)
#include <cuda_runtime.h>
#include <cuda_bf16.h>
#include <cstdint>

#define BB   32
#define NN   577
#define CC   768
#define HH   12
#define DD   64
#define MTOK (BB*NN)        // 18464
#define QKVN (3*CC)         // 2304

// Scratch (allocation-free rule: __device__ globals)
__device__ float g_Q[(size_t)BB*HH*NN*DD];
__device__ float g_K[(size_t)BB*HH*NN*DD];
__device__ float g_V[(size_t)BB*HH*NN*DD];
__device__ float g_att[(size_t)MTOK*CC];

// ---------------------------------------------------------------------------
// tf32 helpers
// ---------------------------------------------------------------------------
__device__ __forceinline__ uint32_t f2tf32(float x) {
    uint32_t r; asm("cvt.rna.tf32.f32 %0, %1;" : "=r"(r) : "f"(x)); return r;
}
__device__ __forceinline__ float tf32f(float x) {
    uint32_t r; asm("cvt.rna.tf32.f32 %0, %1;" : "=r"(r) : "f"(x));
    return __uint_as_float(r);
}
__device__ __forceinline__ void mma_tf32(float (&d)[4], const uint32_t (&a)[4],
                                         const uint32_t b0, const uint32_t b1,
                                         const float (&c)[4]) {
    asm volatile(
        "mma.sync.aligned.m16n8k8.row.col.f32.tf32.tf32.f32 "
        "{%0,%1,%2,%3}, {%4,%5,%6,%7}, {%8,%9}, {%10,%11,%12,%13};\n"
        : "=f"(d[0]), "=f"(d[1]), "=f"(d[2]), "=f"(d[3])
        : "r"(a[0]), "r"(a[1]), "r"(a[2]), "r"(a[3]),
          "r"(b0), "r"(b1),
          "f"(c[0]), "f"(c[1]), "f"(c[2]), "f"(c[3]));
}

// ---------------------------------------------------------------------------
// Tensor-core GEMM mainloop: 128(M) x 128(N) tile, BK=16, 256 thr (8 warps).
// Warp layout: warp_m = wid&3 (32 rows = 2 m-frags), warp_n = wid>>2 (64 cols
// = 8 n-frags). Double-buffered SMEM; tf32 conversion at SMEM-store time.
// As stride 20 (m-major [128][16+4]); Bs stride 136 (k-major [16][128+8]).
// ---------------------------------------------------------------------------
#define AS_STR 20
#define BS_STR 136
#define AS_SZ  (128*AS_STR)
#define BS_SZ  (16*BS_STR)

__device__ __forceinline__ void gemm_tc(
    const float* __restrict__ A, const float* __restrict__ W,
    int M, int Kdim, int Nld, int m0, int n0,
    float (&acc)[2][8][4], float* __restrict__ As, float* __restrict__ Bs)
{
    const int tid  = threadIdx.x;
    const int lane = tid & 31;
    const int wid  = tid >> 5;
    const int grp  = lane >> 2;
    const int tid4 = lane & 3;
    const int wm32 = (wid & 3) * 32;
    const int wn64 = (wid >> 2) * 64;

    // GMEM staging indices
    const int ar0 = tid >> 2,  ac4 = (tid & 3) * 4;      // A: (row, kcol) pairs
    const int bk0 = tid >> 5,  bc4 = (tid & 31) * 4;     // B: (krow, ncol)

    float4 ra[2], rb[2];
    const int KT = Kdim / 16;

    auto load_regs = [&](int t) {
        int k0 = t * 16;
        #pragma unroll
        for (int i = 0; i < 2; i++) {
            int row = ar0 + i * 64;
            int gr = m0 + row;
            ra[i] = (gr < M) ? *(const float4*)(A + (size_t)gr * Kdim + k0 + ac4)
                             : make_float4(0.f, 0.f, 0.f, 0.f);
            int kr = bk0 + i * 8;
            rb[i] = *(const float4*)(W + (size_t)(k0 + kr) * Nld + n0 + bc4);
        }
    };
    auto store_smem = [&](int buf) {
        float* as = As + buf * AS_SZ;
        float* bs = Bs + buf * BS_SZ;
        #pragma unroll
        for (int i = 0; i < 2; i++) {
            int row = ar0 + i * 64;
            float4 v = ra[i];
            v.x = tf32f(v.x); v.y = tf32f(v.y); v.z = tf32f(v.z); v.w = tf32f(v.w);
            *(float4*)(as + row * AS_STR + ac4) = v;
            int kr = bk0 + i * 8;
            float4 w4 = rb[i];
            w4.x = tf32f(w4.x); w4.y = tf32f(w4.y); w4.z = tf32f(w4.z); w4.w = tf32f(w4.w);
            *(float4*)(bs + kr * BS_STR + bc4) = w4;
        }
    };

    load_regs(0);
    store_smem(0);
    __syncthreads();

    for (int t = 0; t < KT; t++) {
        if (t + 1 < KT) load_regs(t + 1);

        const float* as = As + (t & 1) * AS_SZ;
        const float* bs = Bs + (t & 1) * BS_SZ;
        #pragma unroll
        for (int ks = 0; ks < 16; ks += 8) {
            uint32_t a[2][4];
            #pragma unroll
            for (int mt = 0; mt < 2; mt++) {
                int r = wm32 + mt * 16 + grp;
                a[mt][0] = __float_as_uint(as[r * AS_STR + ks + tid4]);
                a[mt][1] = __float_as_uint(as[(r + 8) * AS_STR + ks + tid4]);
                a[mt][2] = __float_as_uint(as[r * AS_STR + ks + tid4 + 4]);
                a[mt][3] = __float_as_uint(as[(r + 8) * AS_STR + ks + tid4 + 4]);
            }
            #pragma unroll
            for (int nt = 0; nt < 8; nt++) {
                int c = wn64 + nt * 8 + grp;
                uint32_t b0 = __float_as_uint(bs[(ks + tid4) * BS_STR + c]);
                uint32_t b1 = __float_as_uint(bs[(ks + tid4 + 4) * BS_STR + c]);
                #pragma unroll
                for (int mt = 0; mt < 2; mt++)
                    mma_tf32(acc[mt][nt], a[mt], b0, b1, acc[mt][nt]);
            }
        }
        __syncthreads();
        if (t + 1 < KT) {
            store_smem((t + 1) & 1);
            __syncthreads();
        }
    }
}

// ---------------------------------------------------------------------------
// Kernel 1: QKV GEMM + bias + RoPE + q-scale, scatter to [B,H,N,D].
// Each warp's 64-col span is exactly one head: the RoPE pair (d, d^32) lives
// in the same thread at n-tile nt^4, same register index.
// ---------------------------------------------------------------------------
__global__ void __launch_bounds__(256) qkv_kernel(
    const float* __restrict__ x, const float* __restrict__ w,
    const float* __restrict__ bias,
    const float* __restrict__ rsin, const float* __restrict__ rcos)
{
    __shared__ float As[2 * AS_SZ];
    __shared__ float Bs[2 * BS_SZ];
    float acc[2][8][4] = {};

    const int m0 = blockIdx.y * 128;
    const int n0 = blockIdx.x * 128;

    gemm_tc(x, w, MTOK, CC, QKVN, m0, n0, acc, As, Bs);

    const int lane = threadIdx.x & 31;
    const int wid  = threadIdx.x >> 5;
    const int grp  = lane >> 2;
    const int tid4 = lane & 3;
    const int wm32 = (wid & 3) * 32;
    const int wn64 = (wid >> 2) * 64;

    const int which = n0 / CC;                       // 0=q,1=k,2=v
    float* dst = (which == 0) ? g_Q : ((which == 1) ? g_K : g_V);
    const int h = ((n0 + wn64) % CC) / DD;
    const bool is_v = (which == 2);
    const bool is_q = (which == 0);

    // pass 1: add bias in place
    #pragma unroll
    for (int nt = 0; nt < 8; nt++) {
        int c = n0 + wn64 + nt * 8 + 2 * tid4;
        float b0 = bias[c], b1 = bias[c + 1];
        #pragma unroll
        for (int mt = 0; mt < 2; mt++) {
            acc[mt][nt][0] += b0; acc[mt][nt][1] += b1;
            acc[mt][nt][2] += b0; acc[mt][nt][3] += b1;
        }
    }

    // pass 2: RoPE + scale + scatter (reads acc, never writes it)
    #pragma unroll
    for (int mt = 0; mt < 2; mt++) {
        #pragma unroll
        for (int rr = 0; rr < 2; rr++) {
            int m = m0 + wm32 + mt * 16 + grp + rr * 8;
            if (m >= MTOK) continue;
            int bb = m / NN;
            int n  = m - bb * NN;
            #pragma unroll
            for (int nt = 0; nt < 8; nt++) {
                int d0 = nt * 8 + 2 * tid4;
                float v0 = acc[mt][nt][2 * rr];
                float v1 = acc[mt][nt][2 * rr + 1];
                float o0 = v0, o1 = v1;
                if (!is_v && n > 0) {
                    float p0 = acc[mt][nt ^ 4][2 * rr];
                    float p1 = acc[mt][nt ^ 4][2 * rr + 1];
                    float sgn = (nt < 4) ? -1.f : 1.f;
                    float c0 = rcos[(n - 1) * DD + d0],     s0 = rsin[(n - 1) * DD + d0];
                    float c1 = rcos[(n - 1) * DD + d0 + 1], s1 = rsin[(n - 1) * DD + d0 + 1];
                    o0 = v0 * c0 + sgn * p0 * s0;
                    o1 = v1 * c1 + sgn * p1 * s1;
                }
                if (is_q) { o0 *= 0.125f; o1 *= 0.125f; }
                float2 ov = make_float2(o0, o1);
                *(float2*)(dst + (((size_t)bb * HH + h) * NN + n) * DD + d0) = ov;
            }
        }
    }
}

// ---------------------------------------------------------------------------
// Kernel 2: flash attention, tensor cores.
// Block = (128-row q-tile, b*h). 8 warps, warp = 16 q-rows x all 64 cols.
// Q fragments register-resident. K-tiles of 64 rows. P via per-warp SMEM strip.
// ---------------------------------------------------------------------------
#define KS_STR 68
#define VS_STR 72
#define PS_STR 68
#define SM_KS  0
#define SM_VS  (64*KS_STR)              // 4352
#define SM_PS  (SM_VS + 64*VS_STR)      // 8960
#define ATTN_SMEM_FLOATS (SM_PS + 128*PS_STR)
#define ATTN_SMEM_BYTES  (ATTN_SMEM_FLOATS*4)   // 70656

__global__ void __launch_bounds__(256) attn_kernel()
{
    extern __shared__ float sm[];
    float* Ks = sm + SM_KS;
    float* Vs = sm + SM_VS;
    float* Ps = sm + SM_PS;

    const int tid  = threadIdx.x;
    const int lane = tid & 31;
    const int wid  = tid >> 5;
    const int grp  = lane >> 2;
    const int tid4 = lane & 3;

    const int q0 = blockIdx.x * 128;
    const int bh = blockIdx.y;
    const int b = bh / HH, h = bh - b * HH;

    const float* Qp = g_Q + (size_t)bh * NN * DD;
    const float* Kp = g_K + (size_t)bh * NN * DD;
    const float* Vp = g_V + (size_t)bh * NN * DD;

    // Stage Q tile (128x64) into Ps, zero-padded
    #pragma unroll
    for (int i = 0; i < 8; i++) {
        int pos = i * 256 + tid;           // 2048 float4 slots
        int r = pos >> 4, c4 = (pos & 15) * 4;
        float4 v = make_float4(0.f, 0.f, 0.f, 0.f);
        if (q0 + r < NN) v = *(const float4*)(Qp + (size_t)(q0 + r) * DD + c4);
        *(float4*)(Ps + r * PS_STR + c4) = v;
    }
    __syncthreads();

    // Q fragments (register resident, tf32)
    uint32_t aq[8][4];
    {
        const float* qs = Ps + (wid * 16 + grp) * PS_STR;
        #pragma unroll
        for (int ks = 0; ks < 8; ks++) {
            aq[ks][0] = f2tf32(qs[ks * 8 + tid4]);
            aq[ks][1] = f2tf32(qs[8 * PS_STR + ks * 8 + tid4]);
            aq[ks][2] = f2tf32(qs[ks * 8 + tid4 + 4]);
            aq[ks][3] = f2tf32(qs[8 * PS_STR + ks * 8 + tid4 + 4]);
        }
    }
    // No block sync needed: each warp only reads/writes its own Ps strip below.

    float o[8][4] = {};
    float m_st[2] = {-1e30f, -1e30f};
    float l_st[2] = {0.f, 0.f};

    const int NKT = (NN + 63) / 64;   // 10
    for (int kt = 0; kt < NKT; kt++) {
        int kb = kt * 64;
        __syncthreads();   // prior iteration's reads of Ks/Vs complete
        #pragma unroll
        for (int i = 0; i < 4; i++) {
            int pos = i * 256 + tid;       // 1024 float4 per matrix
            int r = pos >> 4, c4 = (pos & 15) * 4;
            bool valid = (kb + r < NN);
            float4 kv = valid ? *(const float4*)(Kp + (size_t)(kb + r) * DD + c4)
                              : make_float4(0.f, 0.f, 0.f, 0.f);
            float4 vv = valid ? *(const float4*)(Vp + (size_t)(kb + r) * DD + c4)
                              : make_float4(0.f, 0.f, 0.f, 0.f);
            kv.x = tf32f(kv.x); kv.y = tf32f(kv.y); kv.z = tf32f(kv.z); kv.w = tf32f(kv.w);
            vv.x = tf32f(vv.x); vv.y = tf32f(vv.y); vv.z = tf32f(vv.z); vv.w = tf32f(vv.w);
            *(float4*)(Ks + r * KS_STR + c4) = kv;
            *(float4*)(Vs + r * VS_STR + c4) = vv;
        }
        __syncthreads();

        // S = Q K^T : per-warp 16x64 strip, frags s[8][4]
        float s[8][4] = {};
        #pragma unroll
        for (int ks = 0; ks < 8; ks++) {
            #pragma unroll
            for (int nt = 0; nt < 8; nt++) {
                const float* kr = Ks + (nt * 8 + grp) * KS_STR + ks * 8 + tid4;
                uint32_t b0 = __float_as_uint(kr[0]);
                uint32_t b1 = __float_as_uint(kr[4]);
                mma_tf32(s[nt], aq[ks], b0, b1, s[nt]);
            }
        }

        // Mask invalid key columns (only last tile)
        if (kb + 64 > NN) {
            #pragma unroll
            for (int nt = 0; nt < 8; nt++) {
                int c = kb + nt * 8 + 2 * tid4;
                if (c >= NN)     { s[nt][0] = -1e30f; s[nt][2] = -1e30f; }
                if (c + 1 >= NN) { s[nt][1] = -1e30f; s[nt][3] = -1e30f; }
            }
        }

        // Online softmax, rows grp (rr=0) and grp+8 (rr=1)
        #pragma unroll
        for (int rr = 0; rr < 2; rr++) {
            float rm = -1e30f;
            #pragma unroll
            for (int nt = 0; nt < 8; nt++)
                rm = fmaxf(rm, fmaxf(s[nt][2 * rr], s[nt][2 * rr + 1]));
            rm = fmaxf(rm, __shfl_xor_sync(0xffffffffu, rm, 1));
            rm = fmaxf(rm, __shfl_xor_sync(0xffffffffu, rm, 2));
            float m_new = fmaxf(m_st[rr], rm);
            float scale = __expf(m_st[rr] - m_new);
            float rs = 0.f;
            #pragma unroll
            for (int nt = 0; nt < 8; nt++) {
                float p0 = tf32f(__expf(s[nt][2 * rr]     - m_new));
                float p1 = tf32f(__expf(s[nt][2 * rr + 1] - m_new));
                s[nt][2 * rr] = p0; s[nt][2 * rr + 1] = p1;
                rs += p0 + p1;
            }
            rs += __shfl_xor_sync(0xffffffffu, rs, 1);
            rs += __shfl_xor_sync(0xffffffffu, rs, 2);
            m_st[rr] = m_new;
            l_st[rr] = l_st[rr] * scale + rs;
            #pragma unroll
            for (int nt = 0; nt < 8; nt++) {
                o[nt][2 * rr] *= scale; o[nt][2 * rr + 1] *= scale;
            }
        }

        // P -> per-warp private SMEM strip (tf32 bits already)
        {
            float* ps = Ps + (wid * 16 + grp) * PS_STR;
            #pragma unroll
            for (int nt = 0; nt < 8; nt++) {
                *(float2*)(ps + nt * 8 + 2 * tid4) = make_float2(s[nt][0], s[nt][1]);
                *(float2*)(ps + 8 * PS_STR + nt * 8 + 2 * tid4) = make_float2(s[nt][2], s[nt][3]);
            }
        }
        __syncwarp();

        // O += P @ V
        {
            const float* ps = Ps + (wid * 16 + grp) * PS_STR;
            #pragma unroll
            for (int ks = 0; ks < 8; ks++) {
                uint32_t ap[4];
                ap[0] = __float_as_uint(ps[ks * 8 + tid4]);
                ap[1] = __float_as_uint(ps[8 * PS_STR + ks * 8 + tid4]);
                ap[2] = __float_as_uint(ps[ks * 8 + tid4 + 4]);
                ap[3] = __float_as_uint(ps[8 * PS_STR + ks * 8 + tid4 + 4]);
                #pragma unroll
                for (int nt = 0; nt < 8; nt++) {
                    const float* vr = Vs + (ks * 8 + tid4) * VS_STR + nt * 8 + grp;
                    uint32_t b0 = __float_as_uint(vr[0]);
                    uint32_t b1 = __float_as_uint(vr[4 * VS_STR]);
                    mma_tf32(o[nt], ap, b0, b1, o[nt]);
                }
            }
        }
        __syncwarp();
    }

    // Epilogue: O / l -> g_att[B, N, C]
    #pragma unroll
    for (int rr = 0; rr < 2; rr++) {
        int n = q0 + wid * 16 + grp + rr * 8;
        if (n >= NN) continue;
        float inv_l = 1.0f / l_st[rr];
        #pragma unroll
        for (int nt = 0; nt < 8; nt++) {
            int d0 = nt * 8 + 2 * tid4;
            float2 ov = make_float2(o[nt][2 * rr] * inv_l, o[nt][2 * rr + 1] * inv_l);
            *(float2*)(g_att + ((size_t)b * NN + n) * CC + h * DD + d0) = ov;
        }
    }
}

// ---------------------------------------------------------------------------
// Kernel 3: output projection + bias -> d_out
// ---------------------------------------------------------------------------
__global__ void __launch_bounds__(256) proj_kernel(
    const float* __restrict__ w, const float* __restrict__ bias,
    float* __restrict__ out)
{
    __shared__ float As[2 * AS_SZ];
    __shared__ float Bs[2 * BS_SZ];
    float acc[2][8][4] = {};

    const int m0 = blockIdx.y * 128;
    const int n0 = blockIdx.x * 128;

    gemm_tc(g_att, w, MTOK, CC, CC, m0, n0, acc, As, Bs);

    const int lane = threadIdx.x & 31;
    const int wid  = threadIdx.x >> 5;
    const int grp  = lane >> 2;
    const int tid4 = lane & 3;
    const int wm32 = (wid & 3) * 32;
    const int wn64 = (wid >> 2) * 64;

    #pragma unroll
    for (int mt = 0; mt < 2; mt++) {
        #pragma unroll
        for (int rr = 0; rr < 2; rr++) {
            int r = m0 + wm32 + mt * 16 + grp + rr * 8;
            if (r >= MTOK) continue;
            #pragma unroll
            for (int nt = 0; nt < 8; nt++) {
                int c = n0 + wn64 + nt * 8 + 2 * tid4;
                float2 ov = make_float2(acc[mt][nt][2 * rr] + bias[c],
                                        acc[mt][nt][2 * rr + 1] + bias[c + 1]);
                *(float2*)(out + (size_t)r * CC + c) = ov;
            }
        }
    }
}

// ---------------------------------------------------------------------------
extern "C" void kernel_launch(void* const* d_in, const int* in_sizes, int n_in,
                              void* d_out, int out_size)
{
    (void)in_sizes; (void)n_in; (void)out_size;
    const float* x      = (const float*)d_in[0];
    const float* w_qkv  = (const float*)d_in[1];
    const float* b_qkv  = (const float*)d_in[2];
    const float* w_proj = (const float*)d_in[3];
    const float* b_proj = (const float*)d_in[4];
    const float* rsin   = (const float*)d_in[5];
    const float* rcos   = (const float*)d_in[6];
    float* out = (float*)d_out;

    cudaFuncSetAttribute(attn_kernel, cudaFuncAttributeMaxDynamicSharedMemorySize,
                         ATTN_SMEM_BYTES);

    dim3 g1(QKVN / 128, (MTOK + 127) / 128);     // 18 x 145
    qkv_kernel<<<g1, 256>>>(x, w_qkv, b_qkv, rsin, rcos);

    dim3 g2((NN + 127) / 128, BB * HH);          // 5 x 384
    attn_kernel<<<g2, 256, ATTN_SMEM_BYTES>>>();

    dim3 g3(CC / 128, (MTOK + 127) / 128);       // 6 x 145
    proj_kernel<<<g3, 256>>>(w_proj, b_proj, out);
}

// round 4
// speedup vs baseline: 1.2262x; 1.2262x over previous
#include <cuda_runtime.h>
#include <cuda_bf16.h>
#include <cstdint>

#define BB   32
#define NN   577
#define CC   768
#define HH   12
#define DD   64
#define MTOK (BB*NN)        // 18464
#define QKVN (3*CC)         // 2304

// Scratch (allocation-free rule: __device__ globals)
__device__ float g_Q[(size_t)BB*HH*NN*DD];
__device__ float g_K[(size_t)BB*HH*NN*DD];
__device__ float g_V[(size_t)BB*HH*NN*DD];
__device__ float g_att[(size_t)MTOK*CC];
__device__ float g_x[(size_t)MTOK*CC];        // tf32-rounded copy of x
__device__ float g_wqkv[(size_t)CC*QKVN];     // tf32-rounded w_qkv
__device__ float g_wproj[(size_t)CC*CC];      // tf32-rounded w_proj

// ---------------------------------------------------------------------------
// tf32 + mma + cp.async helpers
// ---------------------------------------------------------------------------
__device__ __forceinline__ float tf32f(float x) {
    uint32_t r; asm("cvt.rna.tf32.f32 %0, %1;" : "=r"(r) : "f"(x));
    return __uint_as_float(r);
}
__device__ __forceinline__ void mma_tf32(float (&d)[4], const uint32_t (&a)[4],
                                         const uint32_t b0, const uint32_t b1,
                                         const float (&c)[4]) {
    asm volatile(
        "mma.sync.aligned.m16n8k8.row.col.f32.tf32.tf32.f32 "
        "{%0,%1,%2,%3}, {%4,%5,%6,%7}, {%8,%9}, {%10,%11,%12,%13};\n"
        : "=f"(d[0]), "=f"(d[1]), "=f"(d[2]), "=f"(d[3])
        : "r"(a[0]), "r"(a[1]), "r"(a[2]), "r"(a[3]),
          "r"(b0), "r"(b1),
          "f"(c[0]), "f"(c[1]), "f"(c[2]), "f"(c[3]));
}
__device__ __forceinline__ void cp16(uint32_t saddr, const void* gptr, int sz) {
    asm volatile("cp.async.cg.shared.global [%0], [%1], 16, %2;\n"
                 :: "r"(saddr), "l"(gptr), "r"(sz));
}
#define CP_COMMIT() asm volatile("cp.async.commit_group;\n")
template<int N> __device__ __forceinline__ void cp_wait() {
    asm volatile("cp.async.wait_group %0;\n" :: "n"(N));
}

// ---------------------------------------------------------------------------
// Pre-convert kernel: fp32 -> tf32-rounded fp32 (vectorized)
// ---------------------------------------------------------------------------
__global__ void cvt_kernel(const float4* __restrict__ src, float4* __restrict__ dst, int n4) {
    int i = blockIdx.x * blockDim.x + threadIdx.x;
    if (i < n4) {
        float4 v = src[i];
        v.x = tf32f(v.x); v.y = tf32f(v.y); v.z = tf32f(v.z); v.w = tf32f(v.w);
        dst[i] = v;
    }
}

// ---------------------------------------------------------------------------
// GEMM mainloop: 128x128 block, 4 warps (warp tile 64x64), BK=16, 3-stage
// cp.async pipeline. Operands are pre-converted tf32 (no cvt in loop).
// As m-major [128][20]; Bs k-major [16][136]. All frag loads conflict-free.
// ---------------------------------------------------------------------------
#define AS_STR 20
#define BS_STR 136
#define AS_SZ  (128*AS_STR)          // 2560 floats
#define BS_SZ  (16*BS_STR)           // 2176 floats
#define STAGE_SZ (AS_SZ + BS_SZ)     // 4736 floats
#define GEMM_SMEM_BYTES (3*STAGE_SZ*4)  // 56832

__device__ __forceinline__ void gemm_cp(
    const float* __restrict__ A, const float* __restrict__ W,
    int M, int Kdim, int Nld, int m0, int n0,
    float (&acc)[4][8][4], float* __restrict__ sm)
{
    const int tid  = threadIdx.x;
    const int lane = tid & 31;
    const int wid  = tid >> 5;
    const int grp  = lane >> 2;
    const int tid4 = lane & 3;
    const int wm   = (wid & 1) * 64;
    const int wn   = (wid >> 1) * 64;

    // staging coords (128 threads): A row = tid>>2 (+32i), 16B chunk = tid&3
    const int arow = tid >> 2;
    const int achk = (tid & 3) * 4;
    const int bkr  = tid >> 5;
    const int bnc  = (tid & 31) * 4;

    const uint32_t s_base = (uint32_t)__cvta_generic_to_shared(sm);
    const int KT = Kdim / 16;

    auto issue = [&](int t, int buf) {
        int k0 = t * 16;
        uint32_t as = s_base + (uint32_t)(buf * STAGE_SZ) * 4u;
        uint32_t bs = as + AS_SZ * 4u;
        #pragma unroll
        for (int i = 0; i < 4; i++) {
            int row = arow + 32 * i;
            int gr  = m0 + row;
            int grs = (gr < M) ? gr : 0;
            cp16(as + (uint32_t)(row * AS_STR + achk) * 4u,
                 A + (size_t)grs * Kdim + k0 + achk, (gr < M) ? 16 : 0);
        }
        #pragma unroll
        for (int i = 0; i < 4; i++) {
            int kr = bkr + 4 * i;
            cp16(bs + (uint32_t)(kr * BS_STR + bnc) * 4u,
                 W + (size_t)(k0 + kr) * Nld + n0 + bnc, 16);
        }
    };

    issue(0, 0); CP_COMMIT();
    issue(1, 1); CP_COMMIT();

    for (int t = 0; t < KT; t++) {
        cp_wait<1>();
        __syncthreads();           // stage t resident; all warps done with buf (t+2)%3
        if (t + 2 < KT) issue(t + 2, (t + 2) % 3);
        CP_COMMIT();

        const float* as = sm + (t % 3) * STAGE_SZ;
        const float* bs = as + AS_SZ;
        #pragma unroll
        for (int ks = 0; ks < 16; ks += 8) {
            uint32_t a[4][4];
            #pragma unroll
            for (int mt = 0; mt < 4; mt++) {
                int r = wm + mt * 16 + grp;
                a[mt][0] = __float_as_uint(as[r * AS_STR + ks + tid4]);
                a[mt][1] = __float_as_uint(as[(r + 8) * AS_STR + ks + tid4]);
                a[mt][2] = __float_as_uint(as[r * AS_STR + ks + tid4 + 4]);
                a[mt][3] = __float_as_uint(as[(r + 8) * AS_STR + ks + tid4 + 4]);
            }
            #pragma unroll
            for (int nt = 0; nt < 8; nt++) {
                int c = wn + nt * 8 + grp;
                uint32_t b0 = __float_as_uint(bs[(ks + tid4) * BS_STR + c]);
                uint32_t b1 = __float_as_uint(bs[(ks + tid4 + 4) * BS_STR + c]);
                #pragma unroll
                for (int mt = 0; mt < 4; mt++)
                    mma_tf32(acc[mt][nt], a[mt], b0, b1, acc[mt][nt]);
            }
        }
    }
}

// ---------------------------------------------------------------------------
// Kernel 1: QKV GEMM + bias + RoPE + q-scale, scatter tf32 to [B,H,N,D].
// Warp n-span = 64 = one head; RoPE pair (d, d^32) = acc[mt][nt^4], same regs.
// ---------------------------------------------------------------------------
__global__ void __launch_bounds__(128) qkv_kernel(
    const float* __restrict__ bias,
    const float* __restrict__ rsin, const float* __restrict__ rcos)
{
    extern __shared__ float sm[];
    float acc[4][8][4] = {};
    const int m0 = blockIdx.y * 128;
    const int n0 = blockIdx.x * 128;

    gemm_cp(g_x, g_wqkv, MTOK, CC, QKVN, m0, n0, acc, sm);

    const int lane = threadIdx.x & 31;
    const int wid  = threadIdx.x >> 5;
    const int grp  = lane >> 2;
    const int tid4 = lane & 3;
    const int wm   = (wid & 1) * 64;
    const int wn   = (wid >> 1) * 64;

    const int which = n0 / CC;                     // 0=q,1=k,2=v
    float* dst = (which == 0) ? g_Q : ((which == 1) ? g_K : g_V);
    const int h = ((n0 + wn) % CC) / DD;
    const bool is_v = (which == 2);
    const bool is_q = (which == 0);

    // bias pass (in place)
    #pragma unroll
    for (int nt = 0; nt < 8; nt++) {
        int c = n0 + wn + nt * 8 + 2 * tid4;
        float b0 = bias[c], b1 = bias[c + 1];
        #pragma unroll
        for (int mt = 0; mt < 4; mt++) {
            acc[mt][nt][0] += b0; acc[mt][nt][1] += b1;
            acc[mt][nt][2] += b0; acc[mt][nt][3] += b1;
        }
    }

    // RoPE + scale + tf32 + scatter
    #pragma unroll
    for (int mt = 0; mt < 4; mt++) {
        #pragma unroll
        for (int rr = 0; rr < 2; rr++) {
            int m = m0 + wm + mt * 16 + grp + rr * 8;
            if (m >= MTOK) continue;
            int bb = m / NN;
            int n  = m - bb * NN;
            #pragma unroll
            for (int nt = 0; nt < 8; nt++) {
                int d0 = nt * 8 + 2 * tid4;
                float v0 = acc[mt][nt][2 * rr];
                float v1 = acc[mt][nt][2 * rr + 1];
                float o0 = v0, o1 = v1;
                if (!is_v && n > 0) {
                    float p0 = acc[mt][nt ^ 4][2 * rr];
                    float p1 = acc[mt][nt ^ 4][2 * rr + 1];
                    float sgn = (nt < 4) ? -1.f : 1.f;
                    float c0 = rcos[(n - 1) * DD + d0],     s0 = rsin[(n - 1) * DD + d0];
                    float c1 = rcos[(n - 1) * DD + d0 + 1], s1 = rsin[(n - 1) * DD + d0 + 1];
                    o0 = v0 * c0 + sgn * p0 * s0;
                    o1 = v1 * c1 + sgn * p1 * s1;
                }
                if (is_q) { o0 *= 0.125f; o1 *= 0.125f; }
                float2 ov = make_float2(tf32f(o0), tf32f(o1));
                *(float2*)(dst + (((size_t)bb * HH + h) * NN + n) * DD + d0) = ov;
            }
        }
    }
}

// ---------------------------------------------------------------------------
// Kernel 2: flash attention. Block = 128 q-rows x (b,h); 4 warps, warp = 32
// q-rows x 64 keys/d. Q frags register-resident; K/V double-buffered cp.async.
// ---------------------------------------------------------------------------
#define KS_STR 68
#define VS_STR 72
#define PS_STR 68
#define KV_SZ  (64*KS_STR + 64*VS_STR)        // 8960 floats per stage
#define ATT_PS_OFF (2*KV_SZ)                  // 17920
#define ATT_SMEM_FLOATS (ATT_PS_OFF + 128*PS_STR)  // 26624
#define ATT_SMEM_BYTES  (ATT_SMEM_FLOATS*4)        // 106496

__global__ void __launch_bounds__(128) attn_kernel()
{
    extern __shared__ float sm[];
    float* Ps = sm + ATT_PS_OFF;

    const int tid  = threadIdx.x;
    const int lane = tid & 31;
    const int wid  = tid >> 5;
    const int grp  = lane >> 2;
    const int tid4 = lane & 3;

    const int q0 = blockIdx.x * 128;
    const int bh = blockIdx.y;
    const int b = bh / HH, h = bh - b * HH;

    const float* Qp = g_Q + (size_t)bh * NN * DD;
    const float* Kp = g_K + (size_t)bh * NN * DD;
    const float* Vp = g_V + (size_t)bh * NN * DD;

    const uint32_t s_base = (uint32_t)__cvta_generic_to_shared(sm);
    const uint32_t ps_base = s_base + ATT_PS_OFF * 4u;

    auto issueKV = [&](int t, int buf) {
        int kb = t * 64;
        uint32_t ks = s_base + (uint32_t)(buf * KV_SZ) * 4u;
        uint32_t vs = ks + 64 * KS_STR * 4u;
        #pragma unroll
        for (int i = 0; i < 8; i++) {
            int c = tid + i * 128;
            int row = c >> 4, chk = (c & 15) * 4;
            int gr = kb + row;
            int grs = (gr < NN) ? gr : 0;
            int sz = (gr < NN) ? 16 : 0;
            cp16(ks + (uint32_t)(row * KS_STR + chk) * 4u, Kp + (size_t)grs * DD + chk, sz);
            cp16(vs + (uint32_t)(row * VS_STR + chk) * 4u, Vp + (size_t)grs * DD + chk, sz);
        }
    };

    // Stage Q tile (zero-padded) into Ps
    #pragma unroll
    for (int i = 0; i < 16; i++) {
        int c = tid + i * 128;
        int row = c >> 4, chk = (c & 15) * 4;
        int gr = q0 + row;
        int grs = (gr < NN) ? gr : 0;
        cp16(ps_base + (uint32_t)(row * PS_STR + chk) * 4u,
             Qp + (size_t)grs * DD + chk, (gr < NN) ? 16 : 0);
    }
    CP_COMMIT();                   // group 0 = Q
    issueKV(0, 0); CP_COMMIT();    // group 1 = KV0

    cp_wait<1>();                  // Q done (KV0 may still fly)
    __syncthreads();

    // Q fragments: register-resident, already tf32
    uint32_t aq[2][8][4];
    {
        const float* qs = Ps + (wid * 32) * PS_STR;
        #pragma unroll
        for (int mt = 0; mt < 2; mt++) {
            const float* q2 = qs + (mt * 16 + grp) * PS_STR;
            #pragma unroll
            for (int ks = 0; ks < 8; ks++) {
                aq[mt][ks][0] = __float_as_uint(q2[ks * 8 + tid4]);
                aq[mt][ks][1] = __float_as_uint(q2[8 * PS_STR + ks * 8 + tid4]);
                aq[mt][ks][2] = __float_as_uint(q2[ks * 8 + tid4 + 4]);
                aq[mt][ks][3] = __float_as_uint(q2[8 * PS_STR + ks * 8 + tid4 + 4]);
            }
        }
    }

    float o[2][8][4] = {};
    float m_st[2][2] = {{-1e30f, -1e30f}, {-1e30f, -1e30f}};
    float l_st[2][2] = {{0.f, 0.f}, {0.f, 0.f}};

    const int NKT = (NN + 63) / 64;   // 10
    for (int kt = 0; kt < NKT; kt++) {
        if (kt + 1 < NKT) issueKV(kt + 1, (kt + 1) & 1);
        CP_COMMIT();
        cp_wait<1>();                 // KV(kt) resident
        __syncthreads();

        const float* Ks = sm + (kt & 1) * KV_SZ;
        const float* Vs = Ks + 64 * KS_STR;
        const int kb = kt * 64;

        // S = Q K^T : per warp 32x64, frags s[2][8][4]
        float s[2][8][4] = {};
        #pragma unroll
        for (int ks = 0; ks < 8; ks++) {
            #pragma unroll
            for (int nt = 0; nt < 8; nt++) {
                const float* kr = Ks + (nt * 8 + grp) * KS_STR + ks * 8 + tid4;
                uint32_t b0 = __float_as_uint(kr[0]);
                uint32_t b1 = __float_as_uint(kr[4]);
                mma_tf32(s[0][nt], aq[0][ks], b0, b1, s[0][nt]);
                mma_tf32(s[1][nt], aq[1][ks], b0, b1, s[1][nt]);
            }
        }

        if (kb + 64 > NN) {
            #pragma unroll
            for (int nt = 0; nt < 8; nt++) {
                int c = kb + nt * 8 + 2 * tid4;
                #pragma unroll
                for (int mt = 0; mt < 2; mt++) {
                    if (c >= NN)     { s[mt][nt][0] = -1e30f; s[mt][nt][2] = -1e30f; }
                    if (c + 1 >= NN) { s[mt][nt][1] = -1e30f; s[mt][nt][3] = -1e30f; }
                }
            }
        }

        // online softmax (rows: mt*16 + grp + 8*rr)
        #pragma unroll
        for (int mt = 0; mt < 2; mt++) {
            #pragma unroll
            for (int rr = 0; rr < 2; rr++) {
                float rm = -1e30f;
                #pragma unroll
                for (int nt = 0; nt < 8; nt++)
                    rm = fmaxf(rm, fmaxf(s[mt][nt][2 * rr], s[mt][nt][2 * rr + 1]));
                rm = fmaxf(rm, __shfl_xor_sync(0xffffffffu, rm, 1));
                rm = fmaxf(rm, __shfl_xor_sync(0xffffffffu, rm, 2));
                float m_new = fmaxf(m_st[mt][rr], rm);
                float scale = __expf(m_st[mt][rr] - m_new);
                float rs = 0.f;
                #pragma unroll
                for (int nt = 0; nt < 8; nt++) {
                    float p0 = tf32f(__expf(s[mt][nt][2 * rr]     - m_new));
                    float p1 = tf32f(__expf(s[mt][nt][2 * rr + 1] - m_new));
                    s[mt][nt][2 * rr] = p0; s[mt][nt][2 * rr + 1] = p1;
                    rs += p0 + p1;
                }
                rs += __shfl_xor_sync(0xffffffffu, rs, 1);
                rs += __shfl_xor_sync(0xffffffffu, rs, 2);
                m_st[mt][rr] = m_new;
                l_st[mt][rr] = l_st[mt][rr] * scale + rs;
                #pragma unroll
                for (int nt = 0; nt < 8; nt++) {
                    o[mt][nt][2 * rr] *= scale; o[mt][nt][2 * rr + 1] *= scale;
                }
            }
        }

        // P -> per-warp private strip of Ps (warp-local only)
        {
            float* ps = Ps + (wid * 32) * PS_STR;
            #pragma unroll
            for (int mt = 0; mt < 2; mt++) {
                float* p2 = ps + (mt * 16 + grp) * PS_STR;
                #pragma unroll
                for (int nt = 0; nt < 8; nt++) {
                    *(float2*)(p2 + nt * 8 + 2 * tid4) =
                        make_float2(s[mt][nt][0], s[mt][nt][1]);
                    *(float2*)(p2 + 8 * PS_STR + nt * 8 + 2 * tid4) =
                        make_float2(s[mt][nt][2], s[mt][nt][3]);
                }
            }
        }
        __syncwarp();

        // O += P @ V
        {
            const float* ps = Ps + (wid * 32) * PS_STR;
            #pragma unroll
            for (int ks = 0; ks < 8; ks++) {
                uint32_t ap[2][4];
                #pragma unroll
                for (int mt = 0; mt < 2; mt++) {
                    const float* p2 = ps + (mt * 16 + grp) * PS_STR;
                    ap[mt][0] = __float_as_uint(p2[ks * 8 + tid4]);
                    ap[mt][1] = __float_as_uint(p2[8 * PS_STR + ks * 8 + tid4]);
                    ap[mt][2] = __float_as_uint(p2[ks * 8 + tid4 + 4]);
                    ap[mt][3] = __float_as_uint(p2[8 * PS_STR + ks * 8 + tid4 + 4]);
                }
                #pragma unroll
                for (int nt = 0; nt < 8; nt++) {
                    const float* vr = Vs + (ks * 8 + tid4) * VS_STR + nt * 8 + grp;
                    uint32_t b0 = __float_as_uint(vr[0]);
                    uint32_t b1 = __float_as_uint(vr[4 * VS_STR]);
                    mma_tf32(o[0][nt], ap[0], b0, b1, o[0][nt]);
                    mma_tf32(o[1][nt], ap[1], b0, b1, o[1][nt]);
                }
            }
        }
        __syncthreads();   // all warps done with this KV buffer
    }

    // Epilogue: O / l -> g_att (tf32, feeds proj mma)
    #pragma unroll
    for (int mt = 0; mt < 2; mt++) {
        #pragma unroll
        for (int rr = 0; rr < 2; rr++) {
            int n = q0 + wid * 32 + mt * 16 + grp + rr * 8;
            if (n >= NN) continue;
            float inv_l = 1.0f / l_st[mt][rr];
            #pragma unroll
            for (int nt = 0; nt < 8; nt++) {
                int d0 = nt * 8 + 2 * tid4;
                float2 ov = make_float2(tf32f(o[mt][nt][2 * rr] * inv_l),
                                        tf32f(o[mt][nt][2 * rr + 1] * inv_l));
                *(float2*)(g_att + ((size_t)b * NN + n) * CC + h * DD + d0) = ov;
            }
        }
    }
}

// ---------------------------------------------------------------------------
// Kernel 3: output projection + bias -> d_out (fp32)
// ---------------------------------------------------------------------------
__global__ void __launch_bounds__(128) proj_kernel(
    const float* __restrict__ bias, float* __restrict__ out)
{
    extern __shared__ float sm[];
    float acc[4][8][4] = {};
    const int m0 = blockIdx.y * 128;
    const int n0 = blockIdx.x * 128;

    gemm_cp(g_att, g_wproj, MTOK, CC, CC, m0, n0, acc, sm);

    const int lane = threadIdx.x & 31;
    const int wid  = threadIdx.x >> 5;
    const int grp  = lane >> 2;
    const int tid4 = lane & 3;
    const int wm   = (wid & 1) * 64;
    const int wn   = (wid >> 1) * 64;

    #pragma unroll
    for (int mt = 0; mt < 4; mt++) {
        #pragma unroll
        for (int rr = 0; rr < 2; rr++) {
            int r = m0 + wm + mt * 16 + grp + rr * 8;
            if (r >= MTOK) continue;
            #pragma unroll
            for (int nt = 0; nt < 8; nt++) {
                int c = n0 + wn + nt * 8 + 2 * tid4;
                float2 ov = make_float2(acc[mt][nt][2 * rr] + bias[c],
                                        acc[mt][nt][2 * rr + 1] + bias[c + 1]);
                *(float2*)(out + (size_t)r * CC + c) = ov;
            }
        }
    }
}

// ---------------------------------------------------------------------------
extern "C" void kernel_launch(void* const* d_in, const int* in_sizes, int n_in,
                              void* d_out, int out_size)
{
    (void)in_sizes; (void)n_in; (void)out_size;
    const float* x      = (const float*)d_in[0];
    const float* w_qkv  = (const float*)d_in[1];
    const float* b_qkv  = (const float*)d_in[2];
    const float* w_proj = (const float*)d_in[3];
    const float* b_proj = (const float*)d_in[4];
    const float* rsin   = (const float*)d_in[5];
    const float* rcos   = (const float*)d_in[6];
    float* out = (float*)d_out;

    cudaFuncSetAttribute(qkv_kernel,  cudaFuncAttributeMaxDynamicSharedMemorySize, GEMM_SMEM_BYTES);
    cudaFuncSetAttribute(proj_kernel, cudaFuncAttributeMaxDynamicSharedMemorySize, GEMM_SMEM_BYTES);
    cudaFuncSetAttribute(attn_kernel, cudaFuncAttributeMaxDynamicSharedMemorySize, ATT_SMEM_BYTES);

    float* gx; cudaGetSymbolAddress((void**)&gx, g_x);
    float* gwq; cudaGetSymbolAddress((void**)&gwq, g_wqkv);
    float* gwp; cudaGetSymbolAddress((void**)&gwp, g_wproj);

    int n4x = MTOK * CC / 4;
    int n4q = CC * QKVN / 4;
    int n4p = CC * CC / 4;
    cvt_kernel<<<(n4x + 255) / 256, 256>>>((const float4*)x, (float4*)gx, n4x);
    cvt_kernel<<<(n4q + 255) / 256, 256>>>((const float4*)w_qkv, (float4*)gwq, n4q);
    cvt_kernel<<<(n4p + 255) / 256, 256>>>((const float4*)w_proj, (float4*)gwp, n4p);

    dim3 g1(QKVN / 128, (MTOK + 127) / 128);     // 18 x 145
    qkv_kernel<<<g1, 128, GEMM_SMEM_BYTES>>>(b_qkv, rsin, rcos);

    dim3 g2((NN + 127) / 128, BB * HH);          // 5 x 384
    attn_kernel<<<g2, 128, ATT_SMEM_BYTES>>>();

    dim3 g3(CC / 128, (MTOK + 127) / 128);       // 6 x 145
    proj_kernel<<<g3, 128, GEMM_SMEM_BYTES>>>(b_proj, out);
}

// round 5
// speedup vs baseline: 2.1348x; 1.7410x over previous
#include <cuda_runtime.h>
#include <cuda_fp16.h>
#include <cstdint>

#define BB   32
#define NN   577
#define CC   768
#define HH   12
#define DD   64
#define MTOK (BB*NN)        // 18464
#define QKVN (3*CC)         // 2304

// Scratch (allocation-free rule: __device__ globals) — all fp16
__device__ __half g_Q[(size_t)BB*HH*NN*DD];
__device__ __half g_K[(size_t)BB*HH*NN*DD];
__device__ __half g_V[(size_t)BB*HH*NN*DD];
__device__ __half g_att[(size_t)MTOK*CC];
__device__ __half g_x[(size_t)MTOK*CC];
__device__ __half g_wqkv[(size_t)CC*QKVN];
__device__ __half g_wproj[(size_t)CC*CC];

// ---------------------------------------------------------------------------
// helpers
// ---------------------------------------------------------------------------
__device__ __forceinline__ uint32_t packh2(float a, float b) {
    __half2 h = __floats2half2_rn(a, b);
    return *(uint32_t*)&h;
}
__device__ __forceinline__ void ldsm4(uint32_t (&r)[4], uint32_t saddr) {
    asm volatile("ldmatrix.sync.aligned.m8n8.x4.shared.b16 {%0,%1,%2,%3}, [%4];"
        : "=r"(r[0]), "=r"(r[1]), "=r"(r[2]), "=r"(r[3]) : "r"(saddr));
}
__device__ __forceinline__ void ldsm4t(uint32_t (&r)[4], uint32_t saddr) {
    asm volatile("ldmatrix.sync.aligned.m8n8.x4.trans.shared.b16 {%0,%1,%2,%3}, [%4];"
        : "=r"(r[0]), "=r"(r[1]), "=r"(r[2]), "=r"(r[3]) : "r"(saddr));
}
__device__ __forceinline__ void mma_f16(float (&d)[4], const uint32_t (&a)[4],
                                        uint32_t b0, uint32_t b1,
                                        const float (&c)[4]) {
    asm volatile(
        "mma.sync.aligned.m16n8k16.row.col.f32.f16.f16.f32 "
        "{%0,%1,%2,%3}, {%4,%5,%6,%7}, {%8,%9}, {%10,%11,%12,%13};\n"
        : "=f"(d[0]), "=f"(d[1]), "=f"(d[2]), "=f"(d[3])
        : "r"(a[0]), "r"(a[1]), "r"(a[2]), "r"(a[3]),
          "r"(b0), "r"(b1),
          "f"(c[0]), "f"(c[1]), "f"(c[2]), "f"(c[3]));
}
__device__ __forceinline__ void cp16(uint32_t saddr, const void* gptr, int sz) {
    asm volatile("cp.async.cg.shared.global [%0], [%1], 16, %2;\n"
                 :: "r"(saddr), "l"(gptr), "r"(sz));
}
#define CP_COMMIT() asm volatile("cp.async.commit_group;\n")
template<int N> __device__ __forceinline__ void cp_wait() {
    asm volatile("cp.async.wait_group %0;\n" :: "n"(N));
}

// ---------------------------------------------------------------------------
// Pre-convert: fp32 -> fp16
// ---------------------------------------------------------------------------
__global__ void cvth_kernel(const float4* __restrict__ src, uint2* __restrict__ dst, int n4) {
    int i = blockIdx.x * blockDim.x + threadIdx.x;
    if (i < n4) {
        float4 v = src[i];
        uint2 o;
        o.x = packh2(v.x, v.y);
        o.y = packh2(v.z, v.w);
        dst[i] = o;
    }
}

// ---------------------------------------------------------------------------
// fp16 GEMM mainloop: 128x128 block, 4 warps (64x64 each), BK=16, 3-stage
// cp.async. As [128][24] halves (48B stride, LDSM conflict-free);
// Bs [16][136] halves (272B stride). ldmatrix.x4 (+trans for B).
// ---------------------------------------------------------------------------
#define AS_STR 24
#define BS_STR 136
#define AS_SZ  (128*AS_STR)          // 3072 halves
#define BS_SZ  (16*BS_STR)           // 2176 halves
#define STAGE_SZ (AS_SZ + BS_SZ)     // 5248 halves
#define GEMM_SMEM_BYTES (3*STAGE_SZ*2)  // 31488

__device__ __forceinline__ void gemm_cp(
    const __half* __restrict__ A, const __half* __restrict__ W,
    int M, int Kdim, int Nld, int m0, int n0,
    float (&acc)[4][8][4], __half* __restrict__ sm)
{
    const int tid  = threadIdx.x;
    const int lane = tid & 31;
    const int wid  = tid >> 5;
    const int wm   = (wid & 1) * 64;
    const int wn   = (wid >> 1) * 64;

    // staging coords
    const int arow = tid >> 1;           // 0..63 (rows arow, arow+64)
    const int achk = (tid & 1) * 8;      // half offset within 16-half row
    const int bkr  = tid >> 4;           // 0..7 (k rows bkr, bkr+8)
    const int bnc  = (tid & 15) * 8;     // 0..120

    // ldmatrix lane coords (same pattern for A and B-trans)
    const int lrow = (lane & 7) + ((lane >> 3) & 1) * 8;
    const int lcol = ((lane >> 4) & 1) * 8;

    const uint32_t s_base = (uint32_t)__cvta_generic_to_shared(sm);
    const int KT = Kdim / 16;

    auto issue = [&](int t, int buf) {
        int k0 = t * 16;
        uint32_t as = s_base + (uint32_t)(buf * STAGE_SZ) * 2u;
        uint32_t bs = as + AS_SZ * 2u;
        #pragma unroll
        for (int i = 0; i < 2; i++) {
            int row = arow + 64 * i;
            int gr  = m0 + row;
            int grs = (gr < M) ? gr : 0;
            cp16(as + (uint32_t)(row * AS_STR + achk) * 2u,
                 A + (size_t)grs * Kdim + k0 + achk, (gr < M) ? 16 : 0);
        }
        #pragma unroll
        for (int i = 0; i < 2; i++) {
            int kr = bkr + 8 * i;
            cp16(bs + (uint32_t)(kr * BS_STR + bnc) * 2u,
                 W + (size_t)(k0 + kr) * Nld + n0 + bnc, 16);
        }
    };

    issue(0, 0); CP_COMMIT();
    issue(1, 1); CP_COMMIT();

    for (int t = 0; t < KT; t++) {
        cp_wait<1>();
        __syncthreads();
        if (t + 2 < KT) issue(t + 2, (t + 2) % 3);
        CP_COMMIT();

        const uint32_t as = s_base + (uint32_t)((t % 3) * STAGE_SZ) * 2u;
        const uint32_t bs = as + AS_SZ * 2u;

        uint32_t a[4][4];
        #pragma unroll
        for (int mt = 0; mt < 4; mt++)
            ldsm4(a[mt], as + (uint32_t)((wm + mt * 16 + lrow) * AS_STR + lcol) * 2u);

        #pragma unroll
        for (int ntp = 0; ntp < 4; ntp++) {
            uint32_t bf[4];
            ldsm4t(bf, bs + (uint32_t)(lrow * BS_STR + wn + ntp * 16 + lcol) * 2u);
            #pragma unroll
            for (int mt = 0; mt < 4; mt++) {
                mma_f16(acc[mt][2 * ntp],     a[mt], bf[0], bf[1], acc[mt][2 * ntp]);
                mma_f16(acc[mt][2 * ntp + 1], a[mt], bf[2], bf[3], acc[mt][2 * ntp + 1]);
            }
        }
    }
}

// ---------------------------------------------------------------------------
// Kernel 1: QKV GEMM + bias + RoPE + q-scale, scatter fp16 to [B,H,N,D].
// Warp n-span = 64 = one head; RoPE pair (d, d^32) = acc[mt][nt^4].
// ---------------------------------------------------------------------------
__global__ void __launch_bounds__(128) qkv_kernel(
    const float* __restrict__ bias,
    const float* __restrict__ rsin, const float* __restrict__ rcos)
{
    extern __shared__ __half smh[];
    float acc[4][8][4] = {};
    const int m0 = blockIdx.y * 128;
    const int n0 = blockIdx.x * 128;

    gemm_cp(g_x, g_wqkv, MTOK, CC, QKVN, m0, n0, acc, smh);

    const int lane = threadIdx.x & 31;
    const int wid  = threadIdx.x >> 5;
    const int grp  = lane >> 2;
    const int tid4 = lane & 3;
    const int wm   = (wid & 1) * 64;
    const int wn   = (wid >> 1) * 64;

    const int which = n0 / CC;                     // 0=q,1=k,2=v
    __half* dst = (which == 0) ? g_Q : ((which == 1) ? g_K : g_V);
    const int h = ((n0 + wn) % CC) / DD;
    const bool is_v = (which == 2);
    const bool is_q = (which == 0);

    #pragma unroll
    for (int nt = 0; nt < 8; nt++) {
        int c = n0 + wn + nt * 8 + 2 * tid4;
        float b0 = bias[c], b1 = bias[c + 1];
        #pragma unroll
        for (int mt = 0; mt < 4; mt++) {
            acc[mt][nt][0] += b0; acc[mt][nt][1] += b1;
            acc[mt][nt][2] += b0; acc[mt][nt][3] += b1;
        }
    }

    #pragma unroll
    for (int mt = 0; mt < 4; mt++) {
        #pragma unroll
        for (int rr = 0; rr < 2; rr++) {
            int m = m0 + wm + mt * 16 + grp + rr * 8;
            if (m >= MTOK) continue;
            int bb = m / NN;
            int n  = m - bb * NN;
            #pragma unroll
            for (int nt = 0; nt < 8; nt++) {
                int d0 = nt * 8 + 2 * tid4;
                float v0 = acc[mt][nt][2 * rr];
                float v1 = acc[mt][nt][2 * rr + 1];
                float o0 = v0, o1 = v1;
                if (!is_v && n > 0) {
                    float p0 = acc[mt][nt ^ 4][2 * rr];
                    float p1 = acc[mt][nt ^ 4][2 * rr + 1];
                    float sgn = (nt < 4) ? -1.f : 1.f;
                    float c0 = rcos[(n - 1) * DD + d0],     s0 = rsin[(n - 1) * DD + d0];
                    float c1 = rcos[(n - 1) * DD + d0 + 1], s1 = rsin[(n - 1) * DD + d0 + 1];
                    o0 = v0 * c0 + sgn * p0 * s0;
                    o1 = v1 * c1 + sgn * p1 * s1;
                }
                if (is_q) { o0 *= 0.125f; o1 *= 0.125f; }
                *(uint32_t*)(dst + (((size_t)bb * HH + h) * NN + n) * DD + d0) =
                    packh2(o0, o1);
            }
        }
    }
}

// ---------------------------------------------------------------------------
// Kernel 2: flash attention, fp16 MMA, P register-resident (no SMEM P).
// Block = 128 q rows x (b,h); 4 warps, warp = 32 q rows. K/V double-buffered.
// ---------------------------------------------------------------------------
#define KV_STR 72                           // halves per row (64+8)
#define KV_STAGE (2*64*KV_STR)              // K+V per stage, halves = 9216
#define QS_OFF (2*KV_STAGE)                 // 18432 halves
#define ATT_SMEM_HALVES (QS_OFF + 128*KV_STR)   // 27648
#define ATT_SMEM_BYTES  (ATT_SMEM_HALVES*2)     // 55296

__global__ void __launch_bounds__(128) attn_kernel()
{
    extern __shared__ __half smh[];

    const int tid  = threadIdx.x;
    const int lane = tid & 31;
    const int wid  = tid >> 5;
    const int grp  = lane >> 2;
    const int tid4 = lane & 3;

    const int q0 = blockIdx.x * 128;
    const int bh = blockIdx.y;
    const int b = bh / HH, h = bh - b * HH;

    const __half* Qp = g_Q + (size_t)bh * NN * DD;
    const __half* Kp = g_K + (size_t)bh * NN * DD;
    const __half* Vp = g_V + (size_t)bh * NN * DD;

    const uint32_t s_base = (uint32_t)__cvta_generic_to_shared(smh);
    const uint32_t qs_u = s_base + QS_OFF * 2u;

    auto issueKV = [&](int t, int buf) {
        int kb = t * 64;
        uint32_t ks = s_base + (uint32_t)(buf * KV_STAGE) * 2u;
        uint32_t vs = ks + 64 * KV_STR * 2u;
        #pragma unroll
        for (int i = 0; i < 4; i++) {
            int c = tid + i * 128;
            int row = c >> 3, chk = (c & 7) * 8;
            int gr = kb + row;
            int grs = (gr < NN) ? gr : 0;
            int sz = (gr < NN) ? 16 : 0;
            cp16(ks + (uint32_t)(row * KV_STR + chk) * 2u, Kp + (size_t)grs * DD + chk, sz);
            cp16(vs + (uint32_t)(row * KV_STR + chk) * 2u, Vp + (size_t)grs * DD + chk, sz);
        }
    };

    // Q tile -> smem
    #pragma unroll
    for (int i = 0; i < 8; i++) {
        int c = tid + i * 128;
        int row = c >> 3, chk = (c & 7) * 8;
        int gr = q0 + row;
        int grs = (gr < NN) ? gr : 0;
        cp16(qs_u + (uint32_t)(row * KV_STR + chk) * 2u,
             Qp + (size_t)grs * DD + chk, (gr < NN) ? 16 : 0);
    }
    CP_COMMIT();
    issueKV(0, 0); CP_COMMIT();

    cp_wait<1>();                  // Q resident
    __syncthreads();

    // Q fragments register-resident: aq[mt][kb][4]
    const int lrow = (lane & 7) + ((lane >> 3) & 1) * 8;
    const int lcol = ((lane >> 4) & 1) * 8;
    uint32_t aq[2][4][4];
    #pragma unroll
    for (int mt = 0; mt < 2; mt++)
        #pragma unroll
        for (int kb = 0; kb < 4; kb++)
            ldsm4(aq[mt][kb],
                  qs_u + (uint32_t)((wid * 32 + mt * 16 + lrow) * KV_STR + kb * 16 + lcol) * 2u);

    // K ldsm coords (non-trans): rows = tokens, matrices split d 0/8
    const int krow = (lane & 7) + ((lane >> 4) & 1) * 8;
    const int kcol = ((lane >> 3) & 1) * 8;
    // V ldsm coords (trans): rows = tokens (k), matrices split d-blocks
    const int vrow = (lane & 7) + ((lane >> 3) & 1) * 8;
    const int vcol = ((lane >> 4) & 1) * 8;

    float o[2][8][4] = {};
    float m_st[2][2] = {{-1e30f, -1e30f}, {-1e30f, -1e30f}};
    float l_st[2][2] = {{0.f, 0.f}, {0.f, 0.f}};

    const int NKT = (NN + 63) / 64;   // 10
    for (int kt = 0; kt < NKT; kt++) {
        if (kt + 1 < NKT) issueKV(kt + 1, (kt + 1) & 1);
        CP_COMMIT();
        cp_wait<1>();
        __syncthreads();

        const uint32_t ks_u = s_base + (uint32_t)((kt & 1) * KV_STAGE) * 2u;
        const uint32_t vs_u = ks_u + 64 * KV_STR * 2u;
        const int kb_tok = kt * 64;

        // S = Q K^T
        float s[2][8][4] = {};
        #pragma unroll
        for (int kb = 0; kb < 4; kb++) {
            #pragma unroll
            for (int ntp = 0; ntp < 4; ntp++) {
                uint32_t bf[4];
                ldsm4(bf, ks_u + (uint32_t)((ntp * 16 + krow) * KV_STR + kb * 16 + kcol) * 2u);
                #pragma unroll
                for (int mt = 0; mt < 2; mt++) {
                    mma_f16(s[mt][2 * ntp],     aq[mt][kb], bf[0], bf[1], s[mt][2 * ntp]);
                    mma_f16(s[mt][2 * ntp + 1], aq[mt][kb], bf[2], bf[3], s[mt][2 * ntp + 1]);
                }
            }
        }

        if (kb_tok + 64 > NN) {
            #pragma unroll
            for (int nt = 0; nt < 8; nt++) {
                int c = kb_tok + nt * 8 + 2 * tid4;
                #pragma unroll
                for (int mt = 0; mt < 2; mt++) {
                    if (c >= NN)     { s[mt][nt][0] = -1e30f; s[mt][nt][2] = -1e30f; }
                    if (c + 1 >= NN) { s[mt][nt][1] = -1e30f; s[mt][nt][3] = -1e30f; }
                }
            }
        }

        // online softmax
        #pragma unroll
        for (int mt = 0; mt < 2; mt++) {
            #pragma unroll
            for (int rr = 0; rr < 2; rr++) {
                float rm = -1e30f;
                #pragma unroll
                for (int nt = 0; nt < 8; nt++)
                    rm = fmaxf(rm, fmaxf(s[mt][nt][2 * rr], s[mt][nt][2 * rr + 1]));
                rm = fmaxf(rm, __shfl_xor_sync(0xffffffffu, rm, 1));
                rm = fmaxf(rm, __shfl_xor_sync(0xffffffffu, rm, 2));
                float m_new = fmaxf(m_st[mt][rr], rm);
                float scale = __expf(m_st[mt][rr] - m_new);
                float rs = 0.f;
                #pragma unroll
                for (int nt = 0; nt < 8; nt++) {
                    float p0 = __expf(s[mt][nt][2 * rr]     - m_new);
                    float p1 = __expf(s[mt][nt][2 * rr + 1] - m_new);
                    s[mt][nt][2 * rr] = p0; s[mt][nt][2 * rr + 1] = p1;
                    rs += p0 + p1;
                }
                rs += __shfl_xor_sync(0xffffffffu, rs, 1);
                rs += __shfl_xor_sync(0xffffffffu, rs, 2);
                m_st[mt][rr] = m_new;
                l_st[mt][rr] = l_st[mt][rr] * scale + rs;
                #pragma unroll
                for (int nt = 0; nt < 8; nt++) {
                    o[mt][nt][2 * rr] *= scale; o[mt][nt][2 * rr + 1] *= scale;
                }
            }
        }

        // O += P @ V, P packed directly from S accumulators (register only)
        #pragma unroll
        for (int kk = 0; kk < 4; kk++) {
            uint32_t ap[2][4];
            #pragma unroll
            for (int mt = 0; mt < 2; mt++) {
                ap[mt][0] = packh2(s[mt][2 * kk][0],     s[mt][2 * kk][1]);
                ap[mt][1] = packh2(s[mt][2 * kk][2],     s[mt][2 * kk][3]);
                ap[mt][2] = packh2(s[mt][2 * kk + 1][0], s[mt][2 * kk + 1][1]);
                ap[mt][3] = packh2(s[mt][2 * kk + 1][2], s[mt][2 * kk + 1][3]);
            }
            #pragma unroll
            for (int ntp = 0; ntp < 4; ntp++) {
                uint32_t bf[4];
                ldsm4t(bf, vs_u + (uint32_t)((kk * 16 + vrow) * KV_STR + ntp * 16 + vcol) * 2u);
                #pragma unroll
                for (int mt = 0; mt < 2; mt++) {
                    mma_f16(o[mt][2 * ntp],     ap[mt], bf[0], bf[1], o[mt][2 * ntp]);
                    mma_f16(o[mt][2 * ntp + 1], ap[mt], bf[2], bf[3], o[mt][2 * ntp + 1]);
                }
            }
        }
        __syncthreads();   // all warps done with this KV buffer
    }

    // Epilogue: O / l -> g_att (fp16)
    #pragma unroll
    for (int mt = 0; mt < 2; mt++) {
        #pragma unroll
        for (int rr = 0; rr < 2; rr++) {
            int n = q0 + wid * 32 + mt * 16 + grp + rr * 8;
            if (n >= NN) continue;
            float inv_l = 1.0f / l_st[mt][rr];
            #pragma unroll
            for (int nt = 0; nt < 8; nt++) {
                int d0 = nt * 8 + 2 * tid4;
                *(uint32_t*)(g_att + ((size_t)b * NN + n) * CC + h * DD + d0) =
                    packh2(o[mt][nt][2 * rr] * inv_l, o[mt][nt][2 * rr + 1] * inv_l);
            }
        }
    }
}

// ---------------------------------------------------------------------------
// Kernel 3: output projection + bias -> d_out (fp32)
// ---------------------------------------------------------------------------
__global__ void __launch_bounds__(128) proj_kernel(
    const float* __restrict__ bias, float* __restrict__ out)
{
    extern __shared__ __half smh[];
    float acc[4][8][4] = {};
    const int m0 = blockIdx.y * 128;
    const int n0 = blockIdx.x * 128;

    gemm_cp(g_att, g_wproj, MTOK, CC, CC, m0, n0, acc, smh);

    const int lane = threadIdx.x & 31;
    const int wid  = threadIdx.x >> 5;
    const int grp  = lane >> 2;
    const int tid4 = lane & 3;
    const int wm   = (wid & 1) * 64;
    const int wn   = (wid >> 1) * 64;

    #pragma unroll
    for (int mt = 0; mt < 4; mt++) {
        #pragma unroll
        for (int rr = 0; rr < 2; rr++) {
            int r = m0 + wm + mt * 16 + grp + rr * 8;
            if (r >= MTOK) continue;
            #pragma unroll
            for (int nt = 0; nt < 8; nt++) {
                int c = n0 + wn + nt * 8 + 2 * tid4;
                float2 ov = make_float2(acc[mt][nt][2 * rr] + bias[c],
                                        acc[mt][nt][2 * rr + 1] + bias[c + 1]);
                *(float2*)(out + (size_t)r * CC + c) = ov;
            }
        }
    }
}

// ---------------------------------------------------------------------------
extern "C" void kernel_launch(void* const* d_in, const int* in_sizes, int n_in,
                              void* d_out, int out_size)
{
    (void)in_sizes; (void)n_in; (void)out_size;
    const float* x      = (const float*)d_in[0];
    const float* w_qkv  = (const float*)d_in[1];
    const float* b_qkv  = (const float*)d_in[2];
    const float* w_proj = (const float*)d_in[3];
    const float* b_proj = (const float*)d_in[4];
    const float* rsin   = (const float*)d_in[5];
    const float* rcos   = (const float*)d_in[6];
    float* out = (float*)d_out;

    cudaFuncSetAttribute(qkv_kernel,  cudaFuncAttributeMaxDynamicSharedMemorySize, GEMM_SMEM_BYTES);
    cudaFuncSetAttribute(proj_kernel, cudaFuncAttributeMaxDynamicSharedMemorySize, GEMM_SMEM_BYTES);
    cudaFuncSetAttribute(attn_kernel, cudaFuncAttributeMaxDynamicSharedMemorySize, ATT_SMEM_BYTES);

    __half* gx;  cudaGetSymbolAddress((void**)&gx,  g_x);
    __half* gwq; cudaGetSymbolAddress((void**)&gwq, g_wqkv);
    __half* gwp; cudaGetSymbolAddress((void**)&gwp, g_wproj);

    int n4x = MTOK * CC / 4;
    int n4q = CC * QKVN / 4;
    int n4p = CC * CC / 4;
    cvth_kernel<<<(n4x + 255) / 256, 256>>>((const float4*)x, (uint2*)gx, n4x);
    cvth_kernel<<<(n4q + 255) / 256, 256>>>((const float4*)w_qkv, (uint2*)gwq, n4q);
    cvth_kernel<<<(n4p + 255) / 256, 256>>>((const float4*)w_proj, (uint2*)gwp, n4p);

    dim3 g1(QKVN / 128, (MTOK + 127) / 128);     // 18 x 145
    qkv_kernel<<<g1, 128, GEMM_SMEM_BYTES>>>(b_qkv, rsin, rcos);

    dim3 g2((NN + 127) / 128, BB * HH);          // 5 x 384
    attn_kernel<<<g2, 128, ATT_SMEM_BYTES>>>();

    dim3 g3(CC / 128, (MTOK + 127) / 128);       // 6 x 145
    proj_kernel<<<g3, 128, GEMM_SMEM_BYTES>>>(b_proj, out);
}

// round 7
// speedup vs baseline: 2.3162x; 1.0850x over previous
#include <cuda_runtime.h>
#include <cuda_fp16.h>
#include <cstdint>

#define BB   32
#define NN   577
#define CC   768
#define HH   12
#define DD   64
#define MTOK (BB*NN)        // 18464
#define QKVN (3*CC)         // 2304

// Scratch (allocation-free rule: __device__ globals) — all fp16
__device__ __half g_Q[(size_t)BB*HH*NN*DD];
__device__ __half g_K[(size_t)BB*HH*NN*DD];
__device__ __half g_V[(size_t)BB*HH*NN*DD];
__device__ __half g_att[(size_t)MTOK*CC];
__device__ __half g_x[(size_t)MTOK*CC];
__device__ __half g_wqkv[(size_t)CC*QKVN];
__device__ __half g_wproj[(size_t)CC*CC];

// ---------------------------------------------------------------------------
// helpers
// ---------------------------------------------------------------------------
__device__ __forceinline__ uint32_t packh2(float a, float b) {
    __half2 h = __floats2half2_rn(a, b);
    return *(uint32_t*)&h;
}
__device__ __forceinline__ void ldsm4(uint32_t (&r)[4], uint32_t saddr) {
    asm volatile("ldmatrix.sync.aligned.m8n8.x4.shared.b16 {%0,%1,%2,%3}, [%4];"
        : "=r"(r[0]), "=r"(r[1]), "=r"(r[2]), "=r"(r[3]) : "r"(saddr));
}
__device__ __forceinline__ void ldsm4t(uint32_t (&r)[4], uint32_t saddr) {
    asm volatile("ldmatrix.sync.aligned.m8n8.x4.trans.shared.b16 {%0,%1,%2,%3}, [%4];"
        : "=r"(r[0]), "=r"(r[1]), "=r"(r[2]), "=r"(r[3]) : "r"(saddr));
}
__device__ __forceinline__ void mma_f16(float (&d)[4], const uint32_t (&a)[4],
                                        uint32_t b0, uint32_t b1,
                                        const float (&c)[4]) {
    asm volatile(
        "mma.sync.aligned.m16n8k16.row.col.f32.f16.f16.f32 "
        "{%0,%1,%2,%3}, {%4,%5,%6,%7}, {%8,%9}, {%10,%11,%12,%13};\n"
        : "=f"(d[0]), "=f"(d[1]), "=f"(d[2]), "=f"(d[3])
        : "r"(a[0]), "r"(a[1]), "r"(a[2]), "r"(a[3]),
          "r"(b0), "r"(b1),
          "f"(c[0]), "f"(c[1]), "f"(c[2]), "f"(c[3]));
}
__device__ __forceinline__ void cp16(uint32_t saddr, const void* gptr, int sz) {
    asm volatile("cp.async.cg.shared.global [%0], [%1], 16, %2;\n"
                 :: "r"(saddr), "l"(gptr), "r"(sz));
}
#define CP_COMMIT() asm volatile("cp.async.commit_group;\n")
template<int N> __device__ __forceinline__ void cp_wait() {
    asm volatile("cp.async.wait_group %0;\n" :: "n"(N));
}
__device__ __forceinline__ uint32_t smem_u32(const void* p) {
    uint32_t a;
    asm("{ .reg .u64 t; cvta.to.shared.u64 t, %1; cvt.u32.u64 %0, t; }"
        : "=r"(a) : "l"(p));
    return a;
}

// ---------------------------------------------------------------------------
// Pre-convert: fp32 -> fp16
// ---------------------------------------------------------------------------
__global__ void cvth_kernel(const float4* __restrict__ src, uint2* __restrict__ dst, int n4) {
    int i = blockIdx.x * blockDim.x + threadIdx.x;
    if (i < n4) {
        float4 v = src[i];
        uint2 o;
        o.x = packh2(v.x, v.y);
        o.y = packh2(v.z, v.w);
        dst[i] = o;
    }
}

// ---------------------------------------------------------------------------
// fp16 GEMM mainloop: 128x128 block, 4 warps (64x64 each), BK=32, 3-stage
// cp.async. As [128][40] halves; Bs [32][136] halves. ldmatrix.x4 (+trans).
// Two k16 sub-iterations per stage -> half the barriers of BK=16.
// ---------------------------------------------------------------------------
#define AS_STR 40
#define BS_STR 136
#define AS_SZ  (128*AS_STR)          // 5120 halves
#define BS_SZ  (32*BS_STR)           // 4352 halves
#define STAGE_SZ (AS_SZ + BS_SZ)     // 9472 halves
#define GEMM_SMEM_BYTES (3*STAGE_SZ*2)  // 56832

__device__ __forceinline__ void gemm_cp(
    const __half* __restrict__ A, const __half* __restrict__ W,
    int M, int Kdim, int Nld, int m0, int n0,
    float (&acc)[4][8][4], __half* __restrict__ sm)
{
    const int tid  = threadIdx.x;
    const int lane = tid & 31;
    const int wid  = tid >> 5;
    const int wm   = (wid & 1) * 64;
    const int wn   = (wid >> 1) * 64;

    // staging coords
    const int arow = tid >> 2;           // 0..31 (rows arow + 32i)
    const int achk = (tid & 3) * 8;      // half offset within 32-half row
    const int bkr  = tid >> 4;           // 0..7 (k rows bkr + 8i)
    const int bnc  = (tid & 15) * 8;     // 0..120

    // ldmatrix lane coords
    const int lrow = (lane & 7) + ((lane >> 3) & 1) * 8;
    const int lcol = ((lane >> 4) & 1) * 8;

    const uint32_t s_base = smem_u32(sm);
    const int KT = Kdim / 32;

    auto issue = [&](int t, int buf) {
        int k0 = t * 32;
        uint32_t as = s_base + (uint32_t)(buf * STAGE_SZ) * 2u;
        uint32_t bs = as + AS_SZ * 2u;
        #pragma unroll
        for (int i = 0; i < 4; i++) {
            int row = arow + 32 * i;
            int gr  = m0 + row;
            int grs = (gr < M) ? gr : 0;
            cp16(as + (uint32_t)(row * AS_STR + achk) * 2u,
                 A + (size_t)grs * Kdim + k0 + achk, (gr < M) ? 16 : 0);
        }
        #pragma unroll
        for (int i = 0; i < 4; i++) {
            int kr = bkr + 8 * i;
            cp16(bs + (uint32_t)(kr * BS_STR + bnc) * 2u,
                 W + (size_t)(k0 + kr) * Nld + n0 + bnc, 16);
        }
    };

    issue(0, 0); CP_COMMIT();
    issue(1, 1); CP_COMMIT();

    for (int t = 0; t < KT; t++) {
        cp_wait<1>();
        __syncthreads();
        if (t + 2 < KT) issue(t + 2, (t + 2) % 3);
        CP_COMMIT();

        const uint32_t as = s_base + (uint32_t)((t % 3) * STAGE_SZ) * 2u;
        const uint32_t bs = as + AS_SZ * 2u;

        #pragma unroll
        for (int sub = 0; sub < 2; sub++) {
            uint32_t a[4][4];
            #pragma unroll
            for (int mt = 0; mt < 4; mt++)
                ldsm4(a[mt], as + (uint32_t)((wm + mt * 16 + lrow) * AS_STR
                                             + sub * 16 + lcol) * 2u);
            #pragma unroll
            for (int ntp = 0; ntp < 4; ntp++) {
                uint32_t bf[4];
                ldsm4t(bf, bs + (uint32_t)((sub * 16 + lrow) * BS_STR
                                           + wn + ntp * 16 + lcol) * 2u);
                #pragma unroll
                for (int mt = 0; mt < 4; mt++) {
                    mma_f16(acc[mt][2 * ntp],     a[mt], bf[0], bf[1], acc[mt][2 * ntp]);
                    mma_f16(acc[mt][2 * ntp + 1], a[mt], bf[2], bf[3], acc[mt][2 * ntp + 1]);
                }
            }
        }
    }
}

// ---------------------------------------------------------------------------
// Kernel 1: QKV GEMM + bias + RoPE + q-scale, scatter fp16 to [B,H,N,D].
// Warp n-span = 64 = one head; RoPE pair (d, d^32) = acc[mt][nt^4].
// ---------------------------------------------------------------------------
__global__ void __launch_bounds__(128, 3) qkv_kernel(
    const float* __restrict__ bias,
    const float* __restrict__ rsin, const float* __restrict__ rcos)
{
    extern __shared__ __half smh[];
    float acc[4][8][4] = {};
    const int m0 = blockIdx.y * 128;
    const int n0 = blockIdx.x * 128;

    gemm_cp(g_x, g_wqkv, MTOK, CC, QKVN, m0, n0, acc, smh);

    const int lane = threadIdx.x & 31;
    const int wid  = threadIdx.x >> 5;
    const int grp  = lane >> 2;
    const int tid4 = lane & 3;
    const int wm   = (wid & 1) * 64;
    const int wn   = (wid >> 1) * 64;

    const int which = n0 / CC;                     // 0=q,1=k,2=v
    __half* dst = (which == 0) ? g_Q : ((which == 1) ? g_K : g_V);
    const int h = ((n0 + wn) % CC) / DD;
    const bool is_v = (which == 2);
    const bool is_q = (which == 0);

    #pragma unroll
    for (int nt = 0; nt < 8; nt++) {
        int c = n0 + wn + nt * 8 + 2 * tid4;
        float b0 = bias[c], b1 = bias[c + 1];
        #pragma unroll
        for (int mt = 0; mt < 4; mt++) {
            acc[mt][nt][0] += b0; acc[mt][nt][1] += b1;
            acc[mt][nt][2] += b0; acc[mt][nt][3] += b1;
        }
    }

    #pragma unroll
    for (int mt = 0; mt < 4; mt++) {
        #pragma unroll
        for (int rr = 0; rr < 2; rr++) {
            int m = m0 + wm + mt * 16 + grp + rr * 8;
            if (m >= MTOK) continue;
            int bb = m / NN;
            int n  = m - bb * NN;
            #pragma unroll
            for (int nt = 0; nt < 8; nt++) {
                int d0 = nt * 8 + 2 * tid4;
                float v0 = acc[mt][nt][2 * rr];
                float v1 = acc[mt][nt][2 * rr + 1];
                float o0 = v0, o1 = v1;
                if (!is_v && n > 0) {
                    float p0 = acc[mt][nt ^ 4][2 * rr];
                    float p1 = acc[mt][nt ^ 4][2 * rr + 1];
                    float sgn = (nt < 4) ? -1.f : 1.f;
                    float c0 = rcos[(n - 1) * DD + d0],     s0 = rsin[(n - 1) * DD + d0];
                    float c1 = rcos[(n - 1) * DD + d0 + 1], s1 = rsin[(n - 1) * DD + d0 + 1];
                    o0 = v0 * c0 + sgn * p0 * s0;
                    o1 = v1 * c1 + sgn * p1 * s1;
                }
                if (is_q) { o0 *= 0.125f; o1 *= 0.125f; }
                *(uint32_t*)(dst + (((size_t)bb * HH + h) * NN + n) * DD + d0) =
                    packh2(o0, o1);
            }
        }
    }
}

// ---------------------------------------------------------------------------
// Kernel 2: flash attention, fp16 MMA, P register-resident.
// Block = 128 q rows x (b,h); 8 warps, warp = 16 q rows. K/V double-buffered.
// ---------------------------------------------------------------------------
#define KV_STR 72                           // halves per row (64+8)
#define KV_STAGE (2*64*KV_STR)              // K+V per stage, halves = 9216
#define QS_OFF (2*KV_STAGE)                 // 18432 halves
#define ATT_SMEM_HALVES (QS_OFF + 128*KV_STR)   // 27648
#define ATT_SMEM_BYTES  (ATT_SMEM_HALVES*2)     // 55296

__global__ void __launch_bounds__(256, 2) attn_kernel()
{
    extern __shared__ __half smh[];

    const int tid  = threadIdx.x;
    const int lane = tid & 31;
    const int wid  = tid >> 5;              // 0..7
    const int grp  = lane >> 2;
    const int tid4 = lane & 3;

    const int q0 = blockIdx.x * 128;
    const int bh = blockIdx.y;
    const int b = bh / HH, h = bh - b * HH;

    const __half* Qp = g_Q + (size_t)bh * NN * DD;
    const __half* Kp = g_K + (size_t)bh * NN * DD;
    const __half* Vp = g_V + (size_t)bh * NN * DD;

    const uint32_t s_base = smem_u32(smh);
    const uint32_t qs_u = s_base + QS_OFF * 2u;

    auto issueKV = [&](int t, int buf) {
        int kb = t * 64;
        uint32_t ks = s_base + (uint32_t)(buf * KV_STAGE) * 2u;
        uint32_t vs = ks + 64 * KV_STR * 2u;
        #pragma unroll
        for (int i = 0; i < 2; i++) {
            int c = tid + i * 256;
            int row = c >> 3, chk = (c & 7) * 8;
            int gr = kb + row;
            int grs = (gr < NN) ? gr : 0;
            int sz = (gr < NN) ? 16 : 0;
            cp16(ks + (uint32_t)(row * KV_STR + chk) * 2u, Kp + (size_t)grs * DD + chk, sz);
            cp16(vs + (uint32_t)(row * KV_STR + chk) * 2u, Vp + (size_t)grs * DD + chk, sz);
        }
    };

    // Q tile -> smem
    #pragma unroll
    for (int i = 0; i < 4; i++) {
        int c = tid + i * 256;
        int row = c >> 3, chk = (c & 7) * 8;
        int gr = q0 + row;
        int grs = (gr < NN) ? gr : 0;
        cp16(qs_u + (uint32_t)(row * KV_STR + chk) * 2u,
             Qp + (size_t)grs * DD + chk, (gr < NN) ? 16 : 0);
    }
    CP_COMMIT();
    issueKV(0, 0); CP_COMMIT();

    cp_wait<1>();                  // Q resident
    __syncthreads();

    // Q fragments register-resident: aq[kb][4] (16 q rows per warp)
    const int lrow = (lane & 7) + ((lane >> 3) & 1) * 8;
    const int lcol = ((lane >> 4) & 1) * 8;
    uint32_t aq[4][4];
    #pragma unroll
    for (int kb = 0; kb < 4; kb++)
        ldsm4(aq[kb],
              qs_u + (uint32_t)((wid * 16 + lrow) * KV_STR + kb * 16 + lcol) * 2u);

    const int krow = (lane & 7) + ((lane >> 4) & 1) * 8;
    const int kcol = ((lane >> 3) & 1) * 8;
    const int vrow = (lane & 7) + ((lane >> 3) & 1) * 8;
    const int vcol = ((lane >> 4) & 1) * 8;

    float o[8][4] = {};
    float m_st[2] = {-1e30f, -1e30f};
    float l_st[2] = {0.f, 0.f};

    const int NKT = (NN + 63) / 64;   // 10
    for (int kt = 0; kt < NKT; kt++) {
        if (kt + 1 < NKT) issueKV(kt + 1, (kt + 1) & 1);
        CP_COMMIT();
        cp_wait<1>();
        __syncthreads();

        const uint32_t ks_u = s_base + (uint32_t)((kt & 1) * KV_STAGE) * 2u;
        const uint32_t vs_u = ks_u + 64 * KV_STR * 2u;
        const int kb_tok = kt * 64;

        // S = Q K^T (16 x 64 per warp)
        float s[8][4] = {};
        #pragma unroll
        for (int kb = 0; kb < 4; kb++) {
            #pragma unroll
            for (int ntp = 0; ntp < 4; ntp++) {
                uint32_t bf[4];
                ldsm4(bf, ks_u + (uint32_t)((ntp * 16 + krow) * KV_STR + kb * 16 + kcol) * 2u);
                mma_f16(s[2 * ntp],     aq[kb], bf[0], bf[1], s[2 * ntp]);
                mma_f16(s[2 * ntp + 1], aq[kb], bf[2], bf[3], s[2 * ntp + 1]);
            }
        }

        if (kb_tok + 64 > NN) {
            #pragma unroll
            for (int nt = 0; nt < 8; nt++) {
                int c = kb_tok + nt * 8 + 2 * tid4;
                if (c >= NN)     { s[nt][0] = -1e30f; s[nt][2] = -1e30f; }
                if (c + 1 >= NN) { s[nt][1] = -1e30f; s[nt][3] = -1e30f; }
            }
        }

        // online softmax (rows grp, grp+8)
        #pragma unroll
        for (int rr = 0; rr < 2; rr++) {
            float rm = -1e30f;
            #pragma unroll
            for (int nt = 0; nt < 8; nt++)
                rm = fmaxf(rm, fmaxf(s[nt][2 * rr], s[nt][2 * rr + 1]));
            rm = fmaxf(rm, __shfl_xor_sync(0xffffffffu, rm, 1));
            rm = fmaxf(rm, __shfl_xor_sync(0xffffffffu, rm, 2));
            float m_new = fmaxf(m_st[rr], rm);
            float scale = __expf(m_st[rr] - m_new);
            float rs = 0.f;
            #pragma unroll
            for (int nt = 0; nt < 8; nt++) {
                float p0 = __expf(s[nt][2 * rr]     - m_new);
                float p1 = __expf(s[nt][2 * rr + 1] - m_new);
                s[nt][2 * rr] = p0; s[nt][2 * rr + 1] = p1;
                rs += p0 + p1;
            }
            rs += __shfl_xor_sync(0xffffffffu, rs, 1);
            rs += __shfl_xor_sync(0xffffffffu, rs, 2);
            m_st[rr] = m_new;
            l_st[rr] = l_st[rr] * scale + rs;
            #pragma unroll
            for (int nt = 0; nt < 8; nt++) {
                o[nt][2 * rr] *= scale; o[nt][2 * rr + 1] *= scale;
            }
        }

        // O += P @ V, P packed from S accumulators (register only)
        #pragma unroll
        for (int kk = 0; kk < 4; kk++) {
            uint32_t ap[4];
            ap[0] = packh2(s[2 * kk][0],     s[2 * kk][1]);
            ap[1] = packh2(s[2 * kk][2],     s[2 * kk][3]);
            ap[2] = packh2(s[2 * kk + 1][0], s[2 * kk + 1][1]);
            ap[3] = packh2(s[2 * kk + 1][2], s[2 * kk + 1][3]);
            #pragma unroll
            for (int ntp = 0; ntp < 4; ntp++) {
                uint32_t bf[4];
                ldsm4t(bf, vs_u + (uint32_t)((kk * 16 + vrow) * KV_STR + ntp * 16 + vcol) * 2u);
                mma_f16(o[2 * ntp],     ap, bf[0], bf[1], o[2 * ntp]);
                mma_f16(o[2 * ntp + 1], ap, bf[2], bf[3], o[2 * ntp + 1]);
            }
        }
        __syncthreads();   // all warps done with this KV buffer
    }

    // Epilogue: O / l -> g_att (fp16)
    #pragma unroll
    for (int rr = 0; rr < 2; rr++) {
        int n = q0 + wid * 16 + grp + rr * 8;
        if (n >= NN) continue;
        float inv_l = 1.0f / l_st[rr];
        #pragma unroll
        for (int nt = 0; nt < 8; nt++) {
            int d0 = nt * 8 + 2 * tid4;
            *(uint32_t*)(g_att + ((size_t)b * NN + n) * CC + h * DD + d0) =
                packh2(o[nt][2 * rr] * inv_l, o[nt][2 * rr + 1] * inv_l);
        }
    }
}

// ---------------------------------------------------------------------------
// Kernel 3: output projection + bias -> d_out (fp32)
// ---------------------------------------------------------------------------
__global__ void __launch_bounds__(128, 3) proj_kernel(
    const float* __restrict__ bias, float* __restrict__ out)
{
    extern __shared__ __half smh[];
    float acc[4][8][4] = {};
    const int m0 = blockIdx.y * 128;
    const int n0 = blockIdx.x * 128;

    gemm_cp(g_att, g_wproj, MTOK, CC, CC, m0, n0, acc, smh);

    const int lane = threadIdx.x & 31;
    const int wid  = threadIdx.x >> 5;
    const int grp  = lane >> 2;
    const int tid4 = lane & 3;
    const int wm   = (wid & 1) * 64;
    const int wn   = (wid >> 1) * 64;

    #pragma unroll
    for (int mt = 0; mt < 4; mt++) {
        #pragma unroll
        for (int rr = 0; rr < 2; rr++) {
            int r = m0 + wm + mt * 16 + grp + rr * 8;
            if (r >= MTOK) continue;
            #pragma unroll
            for (int nt = 0; nt < 8; nt++) {
                int c = n0 + wn + nt * 8 + 2 * tid4;
                float2 ov = make_float2(acc[mt][nt][2 * rr] + bias[c],
                                        acc[mt][nt][2 * rr + 1] + bias[c + 1]);
                *(float2*)(out + (size_t)r * CC + c) = ov;
            }
        }
    }
}

// ---------------------------------------------------------------------------
extern "C" void kernel_launch(void* const* d_in, const int* in_sizes, int n_in,
                              void* d_out, int out_size)
{
    (void)in_sizes; (void)n_in; (void)out_size;
    const float* x      = (const float*)d_in[0];
    const float* w_qkv  = (const float*)d_in[1];
    const float* b_qkv  = (const float*)d_in[2];
    const float* w_proj = (const float*)d_in[3];
    const float* b_proj = (const float*)d_in[4];
    const float* rsin   = (const float*)d_in[5];
    const float* rcos   = (const float*)d_in[6];
    float* out = (float*)d_out;

    cudaFuncSetAttribute(qkv_kernel,  cudaFuncAttributeMaxDynamicSharedMemorySize, GEMM_SMEM_BYTES);
    cudaFuncSetAttribute(proj_kernel, cudaFuncAttributeMaxDynamicSharedMemorySize, GEMM_SMEM_BYTES);
    cudaFuncSetAttribute(attn_kernel, cudaFuncAttributeMaxDynamicSharedMemorySize, ATT_SMEM_BYTES);

    __half* gx;  cudaGetSymbolAddress((void**)&gx,  g_x);
    __half* gwq; cudaGetSymbolAddress((void**)&gwq, g_wqkv);
    __half* gwp; cudaGetSymbolAddress((void**)&gwp, g_wproj);

    int n4x = MTOK * CC / 4;
    int n4q = CC * QKVN / 4;
    int n4p = CC * CC / 4;
    cvth_kernel<<<(n4x + 255) / 256, 256>>>((const float4*)x, (uint2*)gx, n4x);
    cvth_kernel<<<(n4q + 255) / 256, 256>>>((const float4*)w_qkv, (uint2*)gwq, n4q);
    cvth_kernel<<<(n4p + 255) / 256, 256>>>((const float4*)w_proj, (uint2*)gwp, n4p);

    dim3 g1(QKVN / 128, (MTOK + 127) / 128);     // 18 x 145
    qkv_kernel<<<g1, 128, GEMM_SMEM_BYTES>>>(b_qkv, rsin, rcos);

    dim3 g2((NN + 127) / 128, BB * HH);          // 5 x 384
    attn_kernel<<<g2, 256, ATT_SMEM_BYTES>>>();

    dim3 g3(CC / 128, (MTOK + 127) / 128);       // 6 x 145
    proj_kernel<<<g3, 128, GEMM_SMEM_BYTES>>>(b_proj, out);
}